// round 8
// baseline (speedup 1.0000x reference)
#include <cuda_runtime.h>
#include <cuda_fp16.h>

#define BB 256
#define SS 2048
#define EE 64
#define HH 128
#define G4 512   // 4*H

// x_proj scratch: [S][B][4H] fp32 = 1.07 GB
__device__ float g_xp[(size_t)SS * BB * G4];

__device__ __forceinline__ float sigm_f(float x) {
    return 1.0f / (1.0f + __expf(-x));
}
__device__ __forceinline__ float tanh_f(float x) {
    return 2.0f / (1.0f + __expf(-2.0f * x)) - 1.0f;
}

// ---- f32x2 packed-math helpers (sm_103a) ------------------------------------
typedef unsigned long long ull;

__device__ __forceinline__ ull fma2(ull a, ull b, ull c) {
    ull d;
    asm("fma.rn.f32x2 %0, %1, %2, %3;" : "=l"(d) : "l"(a), "l"(b), "l"(c));
    return d;
}
// bf16x2 (lo half = w_k, hi half = w_{k+1}) -> f32x2 (w_k, w_{k+1})
__device__ __forceinline__ ull bf2f2(unsigned int w) {
    unsigned int lo = w << 16;
    unsigned int hi = w & 0xFFFF0000u;
    ull r;
    asm("mov.b64 %0, {%1, %2};" : "=l"(r) : "r"(lo), "r"(hi));
    return r;
}
__device__ __forceinline__ float hsum2(ull v) {
    float x, y;
    asm("mov.b64 {%0, %1}, %2;" : "=f"(x), "=f"(y) : "l"(v));
    return x + y;
}
__device__ __forceinline__ unsigned int f2bf2(float hi, float lo) {
    unsigned int r;
    asm("cvt.rn.satfinite.bf16x2.f32 %0, %1, %2;" : "=r"(r) : "f"(hi), "f"(lo));
    return r;
}
__device__ __forceinline__ ull dup2(float x) {
    ull r;
    asm("mov.b64 %0, {%1, %1};" : "=l"(r) : "f"(x));
    return r;
}

// ---------------------------------------------------------------------------
// Kernel 1: x_proj[s][b][f] = dot(inputs[b][s][:], U_all[f][:]) + b_u[f]
// 8 timesteps per CTA: U tile loaded once, reused across s.
// ---------------------------------------------------------------------------
__global__ __launch_bounds__(256) void xproj_kernel(
    const float* __restrict__ inputs,   // [B][S][E]
    const float* __restrict__ U_all,    // [4H][E]
    const float* __restrict__ b_u)      // [4H]
{
    __shared__ float xT[64 * 68];  // [e][b]
    __shared__ float uT[64 * 68];  // [e][f]

    const int s0     = blockIdx.z * 8;
    const int b_base = blockIdx.y * 64;
    const int f_base = blockIdx.x * 64;
    const int tid    = threadIdx.x;
    const int e      = tid & 63;
    const int r0     = tid >> 6;

    #pragma unroll
    for (int i = 0; i < 16; i++) {
        int r = r0 + i * 4;
        uT[e * 68 + r] = U_all[(size_t)(f_base + r) * EE + e];
    }

    const int bi = (tid >> 4) * 4;
    const int fi = (tid & 15) * 4;
    float4 bu = *reinterpret_cast<const float4*>(&b_u[f_base + fi]);

    for (int si = 0; si < 8; si++) {
        const int s = s0 + si;
        __syncthreads();
        #pragma unroll
        for (int i = 0; i < 16; i++) {
            int r = r0 + i * 4;
            xT[e * 68 + r] = inputs[((size_t)(b_base + r) * SS + s) * EE + e];
        }
        __syncthreads();

        ull acc[4][2];
        #pragma unroll
        for (int i = 0; i < 4; i++) { acc[i][0] = 0ULL; acc[i][1] = 0ULL; }

        #pragma unroll 16
        for (int k = 0; k < 64; k++) {
            float4 xv = *reinterpret_cast<const float4*>(&xT[k * 68 + bi]);
            ulonglong2 uvp = *reinterpret_cast<const ulonglong2*>(&uT[k * 68 + fi]);
            float xa[4] = {xv.x, xv.y, xv.z, xv.w};
            #pragma unroll
            for (int i = 0; i < 4; i++) {
                ull xx = dup2(xa[i]);
                acc[i][0] = fma2(xx, uvp.x, acc[i][0]);
                acc[i][1] = fma2(xx, uvp.y, acc[i][1]);
            }
        }

        #pragma unroll
        for (int i = 0; i < 4; i++) {
            size_t o = ((size_t)s * BB + (size_t)(b_base + bi + i)) * G4 + f_base + fi;
            float a0, a1, a2, a3;
            asm("mov.b64 {%0, %1}, %2;" : "=f"(a0), "=f"(a1) : "l"(acc[i][0]));
            asm("mov.b64 {%0, %1}, %2;" : "=f"(a2), "=f"(a3) : "l"(acc[i][1]));
            float4 v;
            v.x = a0 + bu.x;
            v.y = a1 + bu.y;
            v.z = a2 + bu.z;
            v.w = a3 + bu.w;
            *reinterpret_cast<float4*>(&g_xp[o]) = v;
        }
    }
}

// ---------------------------------------------------------------------------
// Kernel 2: scan. 128 CTAs x 512 threads, 2 batch rows per CTA.
// R3 decomposition (thread t: c = t&127, kq = t>>7; quarter-k partials for
// the 4 gate columns of c, both rows, + W_d column c quarter) but with the
// GATE WEIGHTS REGISTER-RESIDENT (64 bf16x2 regs/thread). W_d stays in SMEM
// (stride-20 records). Two barriers per step, SMEM kq-reduction.
// ---------------------------------------------------------------------------
#define SM_WD     0                      // 512*20 words  =  40960 B
#define SM_H      40960                  // 2*128 floats  =   1024 B
#define SM_C      41984                  // 2*128 floats  =   1024 B
#define SM_PREG   43008                  // 4*4*2*128 f   =  16384 B
#define SM_CPART  59392                  // 4*2*128 f     =   4096 B
#define SM_RED    63488                  // 256 floats    =   1024 B
#define SMEM_BYTES 64512

__global__ __launch_bounds__(512, 1) void scan_kernel(
    const float* __restrict__ TI,      // [B][S]
    const float* __restrict__ W_all,   // [4H][H]
    const float* __restrict__ b_all,   // [4H]
    const float* __restrict__ W_d,     // [H][H]
    const float* __restrict__ b_d,     // [H]
    const float* __restrict__ W_out,   // [1][H]
    const float* __restrict__ b_out,   // [1]
    float* __restrict__ out)           // [B]
{
    extern __shared__ char smem[];
    unsigned int* wd2 = reinterpret_cast<unsigned int*>(smem + SM_WD);
    float* hb   = reinterpret_cast<float*>(smem + SM_H);     // [2][128]
    float* cb   = reinterpret_cast<float*>(smem + SM_C);     // [2][128]
    float* preg = reinterpret_cast<float*>(smem + SM_PREG);  // [(kq*4+g)*2+m][128]
    float* cpart= reinterpret_cast<float*>(smem + SM_CPART); // [kq*2+m][128]
    float* red  = reinterpret_cast<float*>(smem + SM_RED);

    const int t  = threadIdx.x;
    const int b0 = blockIdx.x * 2;
    const int c  = t & 127;
    const int kq = t >> 7;      // 0..3 (warp-uniform)

    // ---- GATE WEIGHTS -> 64 registers (bf16x2 per k-pair) ----
    // wreg[g*16+p] covers W_all[g*128+c][kq*32 + 2p .. 2p+1]
    unsigned int wreg[64];
    #pragma unroll
    for (int g = 0; g < 4; g++) {
        #pragma unroll
        for (int p = 0; p < 16; p++) {
            float2 wv = *reinterpret_cast<const float2*>(
                &W_all[(size_t)(g * 128 + c) * HH + kq * 32 + 2 * p]);
            wreg[g * 16 + p] = f2bf2(wv.y, wv.x);
        }
    }

    // ---- W_d -> SMEM stride-20 records ----
    // wd2[(kq*128+c)*20 + p] = bf16x2( W_d[c][kq*32+2p], W_d[c][kq*32+2p+1] )
    for (int u = t; u < 512 * 16; u += 512) {
        int p = u & 15, cc = (u >> 4) & 127, kqq = u >> 11;
        float2 wv = *reinterpret_cast<const float2*>(&W_d[(size_t)cc * HH + kqq * 32 + 2 * p]);
        wd2[(kqq * 128 + cc) * 20 + p] = f2bf2(wv.y, wv.x);
    }
    if (t < 256) { hb[t] = 0.0f; cb[t] = 0.0f; }

    // phase-B constants (threads 0..255: m = t>>7, col = c)
    float ba_r[4] = {0, 0, 0, 0}, bd_r = 0.0f, wout_r = 0.0f;
    if (t < 256) {
        #pragma unroll
        for (int g = 0; g < 4; g++) ba_r[g] = b_all[g * 128 + c];
        bd_r = b_d[c];
        wout_r = W_out[c];
    }
    const float bo = b_out[0];

    __syncthreads();

    const uint4* wdt4 = reinterpret_cast<const uint4*>(wd2 + (kq * 128 + c) * 20);
    const ulonglong2* h0v = reinterpret_cast<const ulonglong2*>(hb + kq * 32);
    const ulonglong2* h1v = reinterpret_cast<const ulonglong2*>(hb + 128 + kq * 32);
    const ulonglong2* c0v = reinterpret_cast<const ulonglong2*>(cb + kq * 32);
    const ulonglong2* c1v = reinterpret_cast<const ulonglong2*>(cb + 128 + kq * 32);

    float out_acc = 0.0f;

    for (int s = 0; s < SS; s++) {
        // prefetch phase-B globals (hidden under phase A)
        float xpv[4], ti = 0.0f;
        if (t < 256) {
            const int m = t >> 7;
            size_t xb = ((size_t)s * BB + b0 + m) * G4 + c;
            #pragma unroll
            for (int g = 0; g < 4; g++) xpv[g] = g_xp[xb + g * 128];
            ti = TI[(size_t)(b0 + m) * SS + s];
        }

        // wd weights for this step: 4 x LDS.128
        uint4 wdv[4];
        #pragma unroll
        for (int q = 0; q < 4; q++) wdv[q] = wdt4[q];
        const unsigned int* wdw = reinterpret_cast<const unsigned int*>(wdv);

        // ---- Phase A: quarter-k partial dots (weights from registers) ----
        ull acc0[4] = {0ULL, 0ULL, 0ULL, 0ULL};
        ull acc1[4] = {0ULL, 0ULL, 0ULL, 0ULL};
        ull d0 = 0ULL, d1 = 0ULL;

        #pragma unroll
        for (int p2 = 0; p2 < 8; p2++) {
            ulonglong2 hh0 = h0v[p2];
            ulonglong2 hh1 = h1v[p2];
            #pragma unroll
            for (int g = 0; g < 4; g++) {
                ull wA = bf2f2(wreg[g * 16 + 2 * p2]);
                ull wB = bf2f2(wreg[g * 16 + 2 * p2 + 1]);
                acc0[g] = fma2(hh0.x, wA, acc0[g]);
                acc0[g] = fma2(hh0.y, wB, acc0[g]);
                acc1[g] = fma2(hh1.x, wA, acc1[g]);
                acc1[g] = fma2(hh1.y, wB, acc1[g]);
            }
            ulonglong2 cc0 = c0v[p2];
            ulonglong2 cc1 = c1v[p2];
            ull dA = bf2f2(wdw[2 * p2]);
            ull dB = bf2f2(wdw[2 * p2 + 1]);
            d0 = fma2(cc0.x, dA, d0);
            d0 = fma2(cc0.y, dB, d0);
            d1 = fma2(cc1.x, dA, d1);
            d1 = fma2(cc1.y, dB, d1);
        }

        #pragma unroll
        for (int g = 0; g < 4; g++) {
            preg[((kq * 4 + g) * 2 + 0) * 128 + c] = hsum2(acc0[g]);
            preg[((kq * 4 + g) * 2 + 1) * 128 + c] = hsum2(acc1[g]);
        }
        cpart[(kq * 2 + 0) * 128 + c] = hsum2(d0);
        cpart[(kq * 2 + 1) * 128 + c] = hsum2(d1);
        __syncthreads();

        // ---- Phase B: gating (threads 0..255; (m, c)) ----
        if (t < 256) {
            const int m = t >> 7;
            float pg[4];
            #pragma unroll
            for (int g = 0; g < 4; g++) {
                pg[g] = preg[((0 * 4 + g) * 2 + m) * 128 + c]
                      + preg[((1 * 4 + g) * 2 + m) * 128 + c]
                      + preg[((2 * 4 + g) * 2 + m) * 128 + c]
                      + preg[((3 * 4 + g) * 2 + m) * 128 + c]
                      + ba_r[g] + xpv[g];
            }
            float fg = sigm_f(pg[0]);
            float ig = sigm_f(pg[1]);
            float og = sigm_f(pg[2]);
            float ct = sigm_f(pg[3]);
            float cp = cpart[(0 * 2 + m) * 128 + c] + cpart[(1 * 2 + m) * 128 + c]
                     + cpart[(2 * 2 + m) * 128 + c] + cpart[(3 * 2 + m) * 128 + c] + bd_r;

            float cs1  = tanh_f(cp);
            float cold = cb[m * 128 + c];
            float cadj = (cold - cs1) + cs1 * ti;
            float cnew = fg * cadj + ig * ct;
            float hnew = og * tanh_f(cnew);
            cb[m * 128 + c] = cnew;
            hb[m * 128 + c] = hnew;
            out_acc += hnew * wout_r;
        }
        __syncthreads();
    }

    // ---- out[b] = sum_s h_s @ W_out + S * b_out ----
    if (t < 256) red[t] = out_acc;
    __syncthreads();
    if (t == 0) {
        float s0 = 0.0f;
        for (int k = 0; k < 128; k++) s0 += red[k];
        out[b0] = s0 + (float)SS * bo;
    }
    if (t == 1) {
        float s1 = 0.0f;
        for (int k = 0; k < 128; k++) s1 += red[128 + k];
        out[b0 + 1] = s1 + (float)SS * bo;
    }
}

// ---------------------------------------------------------------------------
extern "C" void kernel_launch(void* const* d_in, const int* in_sizes, int n_in,
                              void* d_out, int out_size)
{
    const float* inputs = (const float*)d_in[0];
    const float* TI     = (const float*)d_in[1];
    const float* W_all  = (const float*)d_in[2];
    const float* b_all  = (const float*)d_in[3];
    const float* U_all  = (const float*)d_in[4];
    const float* b_u    = (const float*)d_in[5];
    const float* W_d    = (const float*)d_in[6];
    const float* b_d    = (const float*)d_in[7];
    const float* W_out  = (const float*)d_in[8];
    const float* b_out  = (const float*)d_in[9];
    float* out = (float*)d_out;

    xproj_kernel<<<dim3(8, 4, 256), 256>>>(inputs, U_all, b_u);

    cudaFuncSetAttribute(scan_kernel,
                         cudaFuncAttributeMaxDynamicSharedMemorySize, SMEM_BYTES);
    scan_kernel<<<128, 512, SMEM_BYTES>>>(TI, W_all, b_all, W_d, b_d,
                                          W_out, b_out, out);
}

// round 9
// speedup vs baseline: 1.8786x; 1.8786x over previous
#include <cuda_runtime.h>
#include <cuda_fp16.h>
#include <cuda_bf16.h>

#define BB 256
#define SS 2048
#define EE 64
#define HH 128
#define G4 512   // 4*H

// x_proj scratch: [S][B][4H] fp32 = 1.07 GB
__device__ float g_xp[(size_t)SS * BB * G4];

__device__ __forceinline__ float sigm_f(float x) {
    return 1.0f / (1.0f + __expf(-x));
}
__device__ __forceinline__ float tanh_f(float x) {
    return 2.0f / (1.0f + __expf(-2.0f * x)) - 1.0f;
}

// ---- f32x2 packed-math helpers (sm_103a) ------------------------------------
typedef unsigned long long ull;

__device__ __forceinline__ ull fma2(ull a, ull b, ull c) {
    ull d;
    asm("fma.rn.f32x2 %0, %1, %2, %3;" : "=l"(d) : "l"(a), "l"(b), "l"(c));
    return d;
}
// bf16x2 (lo half = v_k, hi half = v_{k+1}) -> f32x2 (v_k, v_{k+1})
__device__ __forceinline__ ull bf2f2(unsigned int w) {
    unsigned int lo = w << 16;
    unsigned int hi = w & 0xFFFF0000u;
    ull r;
    asm("mov.b64 %0, {%1, %2};" : "=l"(r) : "r"(lo), "r"(hi));
    return r;
}
__device__ __forceinline__ float hsum2(ull v) {
    float x, y;
    asm("mov.b64 {%0, %1}, %2;" : "=f"(x), "=f"(y) : "l"(v));
    return x + y;
}
__device__ __forceinline__ unsigned int f2bf2(float hi, float lo) {
    unsigned int r;
    asm("cvt.rn.satfinite.bf16x2.f32 %0, %1, %2;" : "=r"(r) : "f"(hi), "f"(lo));
    return r;
}
__device__ __forceinline__ ull dup2(float x) {
    ull r;
    asm("mov.b64 %0, {%1, %1};" : "=l"(r) : "f"(x));
    return r;
}

// ---------------------------------------------------------------------------
// Kernel 1: x_proj[s][b][f] = dot(inputs[b][s][:], U_all[f][:]) + b_u[f]
// 8 timesteps per CTA: U tile loaded once, reused across s.
// ---------------------------------------------------------------------------
__global__ __launch_bounds__(256) void xproj_kernel(
    const float* __restrict__ inputs,   // [B][S][E]
    const float* __restrict__ U_all,    // [4H][E]
    const float* __restrict__ b_u)      // [4H]
{
    __shared__ float xT[64 * 68];  // [e][b]
    __shared__ float uT[64 * 68];  // [e][f]

    const int s0     = blockIdx.z * 8;
    const int b_base = blockIdx.y * 64;
    const int f_base = blockIdx.x * 64;
    const int tid    = threadIdx.x;
    const int e      = tid & 63;
    const int r0     = tid >> 6;

    #pragma unroll
    for (int i = 0; i < 16; i++) {
        int r = r0 + i * 4;
        uT[e * 68 + r] = U_all[(size_t)(f_base + r) * EE + e];
    }

    const int bi = (tid >> 4) * 4;
    const int fi = (tid & 15) * 4;
    float4 bu = *reinterpret_cast<const float4*>(&b_u[f_base + fi]);

    for (int si = 0; si < 8; si++) {
        const int s = s0 + si;
        __syncthreads();
        #pragma unroll
        for (int i = 0; i < 16; i++) {
            int r = r0 + i * 4;
            xT[e * 68 + r] = inputs[((size_t)(b_base + r) * SS + s) * EE + e];
        }
        __syncthreads();

        ull acc[4][2];
        #pragma unroll
        for (int i = 0; i < 4; i++) { acc[i][0] = 0ULL; acc[i][1] = 0ULL; }

        #pragma unroll 16
        for (int k = 0; k < 64; k++) {
            float4 xv = *reinterpret_cast<const float4*>(&xT[k * 68 + bi]);
            ulonglong2 uvp = *reinterpret_cast<const ulonglong2*>(&uT[k * 68 + fi]);
            float xa[4] = {xv.x, xv.y, xv.z, xv.w};
            #pragma unroll
            for (int i = 0; i < 4; i++) {
                ull xx = dup2(xa[i]);
                acc[i][0] = fma2(xx, uvp.x, acc[i][0]);
                acc[i][1] = fma2(xx, uvp.y, acc[i][1]);
            }
        }

        #pragma unroll
        for (int i = 0; i < 4; i++) {
            size_t o = ((size_t)s * BB + (size_t)(b_base + bi + i)) * G4 + f_base + fi;
            float a0, a1, a2, a3;
            asm("mov.b64 {%0, %1}, %2;" : "=f"(a0), "=f"(a1) : "l"(acc[i][0]));
            asm("mov.b64 {%0, %1}, %2;" : "=f"(a2), "=f"(a3) : "l"(acc[i][1]));
            float4 v;
            v.x = a0 + bu.x;
            v.y = a1 + bu.y;
            v.z = a2 + bu.z;
            v.w = a3 + bu.w;
            *reinterpret_cast<float4*>(&g_xp[o]) = v;
        }
    }
}

// ---------------------------------------------------------------------------
// Kernel 2: scan. 128 CTAs x 512 threads, 2 batch rows per CTA.
// R3 structure (thread t: c = t&127, kq = t>>7; quarter-k partials for the 4
// gate columns of c, both rows, + W_d column c quarter; SMEM kq-reduction;
// 2 barriers/step) with two wavefront cuts:
//   * wd weights in 16 registers (step-invariant)  [-256 wf/step]
//   * h state stored as bf16 in SMEM (c stays fp32; c_old carried in reg)
//     -> h broadcasts halve                          [-256 wf/step]
// ---------------------------------------------------------------------------
#define SM_WG     0                      // 64*512 words = 131072 B
#define SM_HBF    131072                 // 2*128 bf16   =    512 B (pad 1024)
#define SM_C      132096                 // 2*128 floats =   1024 B
#define SM_PREG   133120                 // 4*4*2*128 f  =  16384 B
#define SM_CPART  149504                 // 4*2*128 f    =   4096 B
#define SM_RED    153600                 // 256 floats   =   1024 B
#define SMEM_BYTES 154624

__global__ __launch_bounds__(512, 1) void scan_kernel(
    const float* __restrict__ TI,      // [B][S]
    const float* __restrict__ W_all,   // [4H][H]
    const float* __restrict__ b_all,   // [4H]
    const float* __restrict__ W_d,     // [H][H]
    const float* __restrict__ b_d,     // [H]
    const float* __restrict__ W_out,   // [1][H]
    const float* __restrict__ b_out,   // [1]
    float* __restrict__ out)           // [B]
{
    extern __shared__ char smem[];
    unsigned int* wg2 = reinterpret_cast<unsigned int*>(smem + SM_WG);
    __nv_bfloat16* hbf = reinterpret_cast<__nv_bfloat16*>(smem + SM_HBF); // [2][128]
    float* cb   = reinterpret_cast<float*>(smem + SM_C);     // [2][128] fp32
    float* preg = reinterpret_cast<float*>(smem + SM_PREG);  // [(kq*4+g)*2+m][128]
    float* cpart= reinterpret_cast<float*>(smem + SM_CPART); // [kq*2+m][128]
    float* red  = reinterpret_cast<float*>(smem + SM_RED);

    const int t  = threadIdx.x;
    const int b0 = blockIdx.x * 2;
    const int c  = t & 127;
    const int kq = t >> 7;      // 0..3 (warp-uniform)

    // ---- one-time: pack gate weights into SMEM (R3 layout, conflict-free) ----
    // wg2[r*512 + c*4 + g] = bf16x2( W_all[g*128+c][2r], W_all[g*128+c][2r+1] )
    for (int u = t; u < 64 * 512; u += 512) {
        int r = u >> 9, rem = u & 511;
        int cc = rem >> 2, gg = rem & 3;
        float2 wv = *reinterpret_cast<const float2*>(&W_all[(size_t)(gg * 128 + cc) * HH + 2 * r]);
        wg2[u] = f2bf2(wv.y, wv.x);
    }

    // ---- wd weights -> 16 registers (step-invariant; R6-proven budget) ----
    uint4 wdr[4];
    #pragma unroll
    for (int q = 0; q < 4; q++) {
        unsigned int w[4];
        #pragma unroll
        for (int u = 0; u < 4; u++) {
            int p = q * 4 + u;
            float2 wv = *reinterpret_cast<const float2*>(&W_d[(size_t)c * HH + kq * 32 + 2 * p]);
            w[u] = f2bf2(wv.y, wv.x);
        }
        wdr[q] = make_uint4(w[0], w[1], w[2], w[3]);
    }
    const unsigned int* wdw = reinterpret_cast<const unsigned int*>(wdr);

    if (t < 256) {
        reinterpret_cast<unsigned short*>(hbf)[t] = 0;  // bf16 zero
        cb[t] = 0.0f;
    }

    // phase-B constants (threads 0..255: m = t>>7, col = c)
    float ba_r[4] = {0, 0, 0, 0}, bd_r = 0.0f, wout_r = 0.0f;
    if (t < 256) {
        #pragma unroll
        for (int g = 0; g < 4; g++) ba_r[g] = b_all[g * 128 + c];
        bd_r = b_d[c];
        wout_r = W_out[c];
    }
    const float bo = b_out[0];

    __syncthreads();

    const uint4* wgt4 = reinterpret_cast<const uint4*>(wg2) + kq * 16 * 128 + c;
    // h quarters as bf16: 32 halves = 64B = 4 uint4 per row
    const uint4* h0q = reinterpret_cast<const uint4*>(hbf + kq * 32);
    const uint4* h1q = reinterpret_cast<const uint4*>(hbf + 128 + kq * 32);
    const ulonglong2* c0v = reinterpret_cast<const ulonglong2*>(cb + kq * 32);
    const ulonglong2* c1v = reinterpret_cast<const ulonglong2*>(cb + 128 + kq * 32);

    float out_acc = 0.0f;
    float c_reg = 0.0f;   // carried cell state for gating thread (m = t>>7, c)

    for (int s = 0; s < SS; s++) {
        // prefetch phase-B globals (hidden under phase A)
        float xpv[4], ti = 0.0f;
        if (t < 256) {
            const int m = t >> 7;
            size_t xb = ((size_t)s * BB + b0 + m) * G4 + c;
            #pragma unroll
            for (int g = 0; g < 4; g++) xpv[g] = g_xp[xb + g * 128];
            ti = TI[(size_t)(b0 + m) * SS + s];
        }

        // ---- Phase A: quarter-k partial dots ----
        ull acc0[4] = {0ULL, 0ULL, 0ULL, 0ULL};
        ull acc1[4] = {0ULL, 0ULL, 0ULL, 0ULL};
        ull d0 = 0ULL, d1 = 0ULL;

        #pragma unroll
        for (int j = 0; j < 4; j++) {          // each j: 4 k-pairs (8 k)
            uint4 hw0 = h0q[j];                // 8 bf16 of h row 0
            uint4 hw1 = h1q[j];                // 8 bf16 of h row 1
            const unsigned int* hw0w = reinterpret_cast<const unsigned int*>(&hw0);
            const unsigned int* hw1w = reinterpret_cast<const unsigned int*>(&hw1);
            #pragma unroll
            for (int p = 0; p < 4; p++) {      // k-pair index within j
                uint4 wv = wgt4[(j * 4 + p) * 128];
                const unsigned int* w = reinterpret_cast<const unsigned int*>(&wv);
                ull hh0 = bf2f2(hw0w[p]);
                ull hh1 = bf2f2(hw1w[p]);
                #pragma unroll
                for (int g = 0; g < 4; g++) {
                    ull wg_ = bf2f2(w[g]);
                    acc0[g] = fma2(hh0, wg_, acc0[g]);
                    acc1[g] = fma2(hh1, wg_, acc1[g]);
                }
            }
            // wd: 4 k-pairs of the c-state (fp32) against register weights
            ulonglong2 ca = c0v[2 * j], cbq = c0v[2 * j + 1];
            ulonglong2 da = c1v[2 * j], dbq = c1v[2 * j + 1];
            ull wdA = bf2f2(wdw[4 * j + 0]);
            ull wdB = bf2f2(wdw[4 * j + 1]);
            ull wdC = bf2f2(wdw[4 * j + 2]);
            ull wdD = bf2f2(wdw[4 * j + 3]);
            d0 = fma2(ca.x, wdA, d0);  d0 = fma2(ca.y, wdB, d0);
            d0 = fma2(cbq.x, wdC, d0); d0 = fma2(cbq.y, wdD, d0);
            d1 = fma2(da.x, wdA, d1);  d1 = fma2(da.y, wdB, d1);
            d1 = fma2(dbq.x, wdC, d1); d1 = fma2(dbq.y, wdD, d1);
        }

        #pragma unroll
        for (int g = 0; g < 4; g++) {
            preg[((kq * 4 + g) * 2 + 0) * 128 + c] = hsum2(acc0[g]);
            preg[((kq * 4 + g) * 2 + 1) * 128 + c] = hsum2(acc1[g]);
        }
        cpart[(kq * 2 + 0) * 128 + c] = hsum2(d0);
        cpart[(kq * 2 + 1) * 128 + c] = hsum2(d1);
        __syncthreads();

        // ---- Phase B: gating (threads 0..255; (m, c)) ----
        if (t < 256) {
            const int m = t >> 7;
            float pg[4];
            #pragma unroll
            for (int g = 0; g < 4; g++) {
                pg[g] = preg[((0 * 4 + g) * 2 + m) * 128 + c]
                      + preg[((1 * 4 + g) * 2 + m) * 128 + c]
                      + preg[((2 * 4 + g) * 2 + m) * 128 + c]
                      + preg[((3 * 4 + g) * 2 + m) * 128 + c]
                      + ba_r[g] + xpv[g];
            }
            float fg = sigm_f(pg[0]);
            float ig = sigm_f(pg[1]);
            float og = sigm_f(pg[2]);
            float ct = sigm_f(pg[3]);
            float cp = cpart[(0 * 2 + m) * 128 + c] + cpart[(1 * 2 + m) * 128 + c]
                     + cpart[(2 * 2 + m) * 128 + c] + cpart[(3 * 2 + m) * 128 + c] + bd_r;

            float cs1  = tanh_f(cp);
            float cadj = (c_reg - cs1) + cs1 * ti;
            float cnew = fg * cadj + ig * ct;
            float hnew = og * tanh_f(cnew);
            c_reg = cnew;

            cb[m * 128 + c] = cnew;                     // fp32 (wd dot input)
            hbf[m * 128 + c] = __float2bfloat16_rn(hnew); // bf16 (gate dot input)
            out_acc += hnew * wout_r;
        }
        __syncthreads();
    }

    // ---- out[b] = sum_s h_s @ W_out + S * b_out ----
    if (t < 256) red[t] = out_acc;
    __syncthreads();
    if (t == 0) {
        float s0 = 0.0f;
        for (int k = 0; k < 128; k++) s0 += red[k];
        out[b0] = s0 + (float)SS * bo;
    }
    if (t == 1) {
        float s1 = 0.0f;
        for (int k = 0; k < 128; k++) s1 += red[128 + k];
        out[b0 + 1] = s1 + (float)SS * bo;
    }
}

// ---------------------------------------------------------------------------
extern "C" void kernel_launch(void* const* d_in, const int* in_sizes, int n_in,
                              void* d_out, int out_size)
{
    const float* inputs = (const float*)d_in[0];
    const float* TI     = (const float*)d_in[1];
    const float* W_all  = (const float*)d_in[2];
    const float* b_all  = (const float*)d_in[3];
    const float* U_all  = (const float*)d_in[4];
    const float* b_u    = (const float*)d_in[5];
    const float* W_d    = (const float*)d_in[6];
    const float* b_d    = (const float*)d_in[7];
    const float* W_out  = (const float*)d_in[8];
    const float* b_out  = (const float*)d_in[9];
    float* out = (float*)d_out;

    xproj_kernel<<<dim3(8, 4, 256), 256>>>(inputs, U_all, b_u);

    cudaFuncSetAttribute(scan_kernel,
                         cudaFuncAttributeMaxDynamicSharedMemorySize, SMEM_BYTES);
    scan_kernel<<<128, 512, SMEM_BYTES>>>(TI, W_all, b_all, W_d, b_d,
                                          W_out, b_out, out);
}

// round 10
// speedup vs baseline: 2.0048x; 1.0672x over previous
#include <cuda_runtime.h>
#include <cuda_fp16.h>
#include <cuda_bf16.h>

#define BB 256
#define SS 2048
#define EE 64
#define HH 128
#define G4 512   // 4*H

// x_proj scratch, GATE-INTERLEAVED: [(s*BB+b)*128 + c]*4 + g   (1.07 GB fp32)
__device__ float g_xp[(size_t)SS * BB * G4];

// ---- fast activations via MUFU.TANH ----------------------------------------
__device__ __forceinline__ float tanh_ap(float x) {
    float r;
    asm("tanh.approx.f32 %0, %1;" : "=f"(r) : "f"(x));
    return r;
}
__device__ __forceinline__ float sigm_f(float x) {
    return fmaf(0.5f, tanh_ap(0.5f * x), 0.5f);
}
__device__ __forceinline__ float tanh_f(float x) {
    return tanh_ap(x);
}

// ---- f32x2 packed-math helpers (sm_103a) ------------------------------------
typedef unsigned long long ull;

__device__ __forceinline__ ull fma2(ull a, ull b, ull c) {
    ull d;
    asm("fma.rn.f32x2 %0, %1, %2, %3;" : "=l"(d) : "l"(a), "l"(b), "l"(c));
    return d;
}
// bf16x2 (lo half = v_k, hi half = v_{k+1}) -> f32x2 (v_k, v_{k+1})
__device__ __forceinline__ ull bf2f2(unsigned int w) {
    unsigned int lo = w << 16;
    unsigned int hi = w & 0xFFFF0000u;
    ull r;
    asm("mov.b64 %0, {%1, %2};" : "=l"(r) : "r"(lo), "r"(hi));
    return r;
}
__device__ __forceinline__ float hsum2(ull v) {
    float x, y;
    asm("mov.b64 {%0, %1}, %2;" : "=f"(x), "=f"(y) : "l"(v));
    return x + y;
}
__device__ __forceinline__ unsigned int f2bf2(float hi, float lo) {
    unsigned int r;
    asm("cvt.rn.satfinite.bf16x2.f32 %0, %1, %2;" : "=r"(r) : "f"(hi), "f"(lo));
    return r;
}
__device__ __forceinline__ ull dup2(float x) {
    ull r;
    asm("mov.b64 %0, {%1, %1};" : "=l"(r) : "f"(x));
    return r;
}

// ---------------------------------------------------------------------------
// Kernel 1: x_proj = inputs @ U_all^T + b_u  (gate-interleaved output layout)
// 8 timesteps per CTA: U tile loaded once, reused across s.
// ---------------------------------------------------------------------------
__global__ __launch_bounds__(256) void xproj_kernel(
    const float* __restrict__ inputs,   // [B][S][E]
    const float* __restrict__ U_all,    // [4H][E]
    const float* __restrict__ b_u)      // [4H]
{
    __shared__ float xT[64 * 68];  // [e][b]
    __shared__ float uT[64 * 68];  // [e][f]

    const int s0     = blockIdx.z * 8;
    const int b_base = blockIdx.y * 64;
    const int f_base = blockIdx.x * 64;
    const int tid    = threadIdx.x;
    const int e      = tid & 63;
    const int r0     = tid >> 6;

    #pragma unroll
    for (int i = 0; i < 16; i++) {
        int r = r0 + i * 4;
        uT[e * 68 + r] = U_all[(size_t)(f_base + r) * EE + e];
    }

    const int bi = (tid >> 4) * 4;
    const int fi = (tid & 15) * 4;
    float4 bu = *reinterpret_cast<const float4*>(&b_u[f_base + fi]);

    for (int si = 0; si < 8; si++) {
        const int s = s0 + si;
        __syncthreads();
        #pragma unroll
        for (int i = 0; i < 16; i++) {
            int r = r0 + i * 4;
            xT[e * 68 + r] = inputs[((size_t)(b_base + r) * SS + s) * EE + e];
        }
        __syncthreads();

        ull acc[4][2];
        #pragma unroll
        for (int i = 0; i < 4; i++) { acc[i][0] = 0ULL; acc[i][1] = 0ULL; }

        #pragma unroll 16
        for (int k = 0; k < 64; k++) {
            float4 xv = *reinterpret_cast<const float4*>(&xT[k * 68 + bi]);
            ulonglong2 uvp = *reinterpret_cast<const ulonglong2*>(&uT[k * 68 + fi]);
            float xa[4] = {xv.x, xv.y, xv.z, xv.w};
            #pragma unroll
            for (int i = 0; i < 4; i++) {
                ull xx = dup2(xa[i]);
                acc[i][0] = fma2(xx, uvp.x, acc[i][0]);
                acc[i][1] = fma2(xx, uvp.y, acc[i][1]);
            }
        }

        #pragma unroll
        for (int i = 0; i < 4; i++) {
            const int b = b_base + bi + i;
            float av[4];
            asm("mov.b64 {%0, %1}, %2;" : "=f"(av[0]), "=f"(av[1]) : "l"(acc[i][0]));
            asm("mov.b64 {%0, %1}, %2;" : "=f"(av[2]), "=f"(av[3]) : "l"(acc[i][1]));
            const float bub[4] = {bu.x, bu.y, bu.z, bu.w};
            #pragma unroll
            for (int u = 0; u < 4; u++) {
                int f = f_base + fi + u;
                int g = f >> 7;
                int c = f & 127;
                g_xp[(((size_t)s * BB + b) * 128 + c) * 4 + g] = av[u] + bub[u];
            }
        }
    }
}

// ---------------------------------------------------------------------------
// Kernel 2: scan (R9 structure). 128 CTAs x 512 threads, 2 batch rows/CTA.
// thread t: c = t&127, kq = t>>7. Gate weights bf16x2 in SMEM (conflict-free),
// wd weights in 16 regs, h state bf16 in SMEM, c state fp32 in SMEM + carried
// in register by gating threads. SMEM kq-reduction, 2 barriers/step.
// Activations via MUFU.TANH. xp read as one LDG.128.
// ---------------------------------------------------------------------------
#define SM_WG     0                      // 64*512 words = 131072 B
#define SM_HBF    131072                 // 2*128 bf16   =    512 B (pad 1024)
#define SM_C      132096                 // 2*128 floats =   1024 B
#define SM_PREG   133120                 // 4*4*2*128 f  =  16384 B
#define SM_CPART  149504                 // 4*2*128 f    =   4096 B
#define SM_RED    153600                 // 256 floats   =   1024 B
#define SMEM_BYTES 154624

__global__ __launch_bounds__(512, 1) void scan_kernel(
    const float* __restrict__ TI,      // [B][S]
    const float* __restrict__ W_all,   // [4H][H]
    const float* __restrict__ b_all,   // [4H]
    const float* __restrict__ W_d,     // [H][H]
    const float* __restrict__ b_d,     // [H]
    const float* __restrict__ W_out,   // [1][H]
    const float* __restrict__ b_out,   // [1]
    float* __restrict__ out)           // [B]
{
    extern __shared__ char smem[];
    unsigned int* wg2 = reinterpret_cast<unsigned int*>(smem + SM_WG);
    __nv_bfloat16* hbf = reinterpret_cast<__nv_bfloat16*>(smem + SM_HBF); // [2][128]
    float* cb   = reinterpret_cast<float*>(smem + SM_C);     // [2][128] fp32
    float* preg = reinterpret_cast<float*>(smem + SM_PREG);  // [(kq*4+g)*2+m][128]
    float* cpart= reinterpret_cast<float*>(smem + SM_CPART); // [kq*2+m][128]
    float* red  = reinterpret_cast<float*>(smem + SM_RED);

    const int t  = threadIdx.x;
    const int b0 = blockIdx.x * 2;
    const int c  = t & 127;
    const int kq = t >> 7;      // 0..3 (warp-uniform)

    // ---- one-time: pack gate weights into SMEM (conflict-free layout) ----
    // wg2[r*512 + c*4 + g] = bf16x2( W_all[g*128+c][2r], W_all[g*128+c][2r+1] )
    for (int u = t; u < 64 * 512; u += 512) {
        int r = u >> 9, rem = u & 511;
        int cc = rem >> 2, gg = rem & 3;
        float2 wv = *reinterpret_cast<const float2*>(&W_all[(size_t)(gg * 128 + cc) * HH + 2 * r]);
        wg2[u] = f2bf2(wv.y, wv.x);
    }

    // ---- wd weights -> 16 registers (step-invariant) ----
    uint4 wdr[4];
    #pragma unroll
    for (int q = 0; q < 4; q++) {
        unsigned int w[4];
        #pragma unroll
        for (int u = 0; u < 4; u++) {
            int p = q * 4 + u;
            float2 wv = *reinterpret_cast<const float2*>(&W_d[(size_t)c * HH + kq * 32 + 2 * p]);
            w[u] = f2bf2(wv.y, wv.x);
        }
        wdr[q] = make_uint4(w[0], w[1], w[2], w[3]);
    }
    const unsigned int* wdw = reinterpret_cast<const unsigned int*>(wdr);

    if (t < 256) {
        reinterpret_cast<unsigned short*>(hbf)[t] = 0;  // bf16 zero
        cb[t] = 0.0f;
    }

    // phase-B constants (threads 0..255: m = t>>7, col = c)
    float ba_r[4] = {0, 0, 0, 0}, bd_r = 0.0f, wout_r = 0.0f;
    if (t < 256) {
        #pragma unroll
        for (int g = 0; g < 4; g++) ba_r[g] = b_all[g * 128 + c];
        bd_r = b_d[c];
        wout_r = W_out[c];
    }
    const float bo = b_out[0];

    __syncthreads();

    const uint4* wgt4 = reinterpret_cast<const uint4*>(wg2) + kq * 16 * 128 + c;
    const uint4* h0q = reinterpret_cast<const uint4*>(hbf + kq * 32);
    const uint4* h1q = reinterpret_cast<const uint4*>(hbf + 128 + kq * 32);
    const ulonglong2* c0v = reinterpret_cast<const ulonglong2*>(cb + kq * 32);
    const ulonglong2* c1v = reinterpret_cast<const ulonglong2*>(cb + 128 + kq * 32);

    float out_acc = 0.0f;
    float c_reg = 0.0f;   // carried cell state for gating thread (m = t>>7, c)

    for (int s = 0; s < SS; s++) {
        // prefetch phase-B globals (hidden under phase A): ONE LDG.128 for xp
        float4 xq = make_float4(0.f, 0.f, 0.f, 0.f);
        float ti = 0.0f;
        if (t < 256) {
            const int m = t >> 7;
            xq = *reinterpret_cast<const float4*>(
                &g_xp[(((size_t)s * BB + b0 + m) * 128 + c) * 4]);
            ti = TI[(size_t)(b0 + m) * SS + s];
        }

        // ---- Phase A: quarter-k partial dots ----
        ull acc0[4] = {0ULL, 0ULL, 0ULL, 0ULL};
        ull acc1[4] = {0ULL, 0ULL, 0ULL, 0ULL};
        ull d0 = 0ULL, d1 = 0ULL;

        #pragma unroll
        for (int j = 0; j < 4; j++) {          // each j: 4 k-pairs (8 k)
            uint4 hw0 = h0q[j];                // 8 bf16 of h row 0
            uint4 hw1 = h1q[j];                // 8 bf16 of h row 1
            const unsigned int* hw0w = reinterpret_cast<const unsigned int*>(&hw0);
            const unsigned int* hw1w = reinterpret_cast<const unsigned int*>(&hw1);
            #pragma unroll
            for (int p = 0; p < 4; p++) {      // k-pair index within j
                uint4 wv = wgt4[(j * 4 + p) * 128];
                const unsigned int* w = reinterpret_cast<const unsigned int*>(&wv);
                ull hh0 = bf2f2(hw0w[p]);
                ull hh1 = bf2f2(hw1w[p]);
                #pragma unroll
                for (int g = 0; g < 4; g++) {
                    ull wg_ = bf2f2(w[g]);
                    acc0[g] = fma2(hh0, wg_, acc0[g]);
                    acc1[g] = fma2(hh1, wg_, acc1[g]);
                }
            }
            // wd: 4 k-pairs of the c-state (fp32) against register weights
            ulonglong2 ca = c0v[2 * j], cbq = c0v[2 * j + 1];
            ulonglong2 da = c1v[2 * j], dbq = c1v[2 * j + 1];
            ull wdA = bf2f2(wdw[4 * j + 0]);
            ull wdB = bf2f2(wdw[4 * j + 1]);
            ull wdC = bf2f2(wdw[4 * j + 2]);
            ull wdD = bf2f2(wdw[4 * j + 3]);
            d0 = fma2(ca.x, wdA, d0);  d0 = fma2(ca.y, wdB, d0);
            d0 = fma2(cbq.x, wdC, d0); d0 = fma2(cbq.y, wdD, d0);
            d1 = fma2(da.x, wdA, d1);  d1 = fma2(da.y, wdB, d1);
            d1 = fma2(dbq.x, wdC, d1); d1 = fma2(dbq.y, wdD, d1);
        }

        #pragma unroll
        for (int g = 0; g < 4; g++) {
            preg[((kq * 4 + g) * 2 + 0) * 128 + c] = hsum2(acc0[g]);
            preg[((kq * 4 + g) * 2 + 1) * 128 + c] = hsum2(acc1[g]);
        }
        cpart[(kq * 2 + 0) * 128 + c] = hsum2(d0);
        cpart[(kq * 2 + 1) * 128 + c] = hsum2(d1);
        __syncthreads();

        // ---- Phase B: gating (threads 0..255; (m, c)) ----
        if (t < 256) {
            const int m = t >> 7;
            const float xpv[4] = {xq.x, xq.y, xq.z, xq.w};
            float pg[4];
            #pragma unroll
            for (int g = 0; g < 4; g++) {
                pg[g] = preg[((0 * 4 + g) * 2 + m) * 128 + c]
                      + preg[((1 * 4 + g) * 2 + m) * 128 + c]
                      + preg[((2 * 4 + g) * 2 + m) * 128 + c]
                      + preg[((3 * 4 + g) * 2 + m) * 128 + c]
                      + ba_r[g] + xpv[g];
            }
            float fg = sigm_f(pg[0]);
            float ig = sigm_f(pg[1]);
            float og = sigm_f(pg[2]);
            float ct = sigm_f(pg[3]);
            float cp = cpart[(0 * 2 + m) * 128 + c] + cpart[(1 * 2 + m) * 128 + c]
                     + cpart[(2 * 2 + m) * 128 + c] + cpart[(3 * 2 + m) * 128 + c] + bd_r;

            float cs1  = tanh_f(cp);
            float cadj = (c_reg - cs1) + cs1 * ti;
            float cnew = fg * cadj + ig * ct;
            float hnew = og * tanh_f(cnew);
            c_reg = cnew;

            cb[m * 128 + c] = cnew;                       // fp32 (wd dot input)
            hbf[m * 128 + c] = __float2bfloat16_rn(hnew); // bf16 (gate dot input)
            out_acc += hnew * wout_r;
        }
        __syncthreads();
    }

    // ---- out[b] = sum_s h_s @ W_out + S * b_out ----
    if (t < 256) red[t] = out_acc;
    __syncthreads();
    if (t == 0) {
        float s0 = 0.0f;
        for (int k = 0; k < 128; k++) s0 += red[k];
        out[b0] = s0 + (float)SS * bo;
    }
    if (t == 1) {
        float s1 = 0.0f;
        for (int k = 0; k < 128; k++) s1 += red[128 + k];
        out[b0 + 1] = s1 + (float)SS * bo;
    }
}

// ---------------------------------------------------------------------------
extern "C" void kernel_launch(void* const* d_in, const int* in_sizes, int n_in,
                              void* d_out, int out_size)
{
    const float* inputs = (const float*)d_in[0];
    const float* TI     = (const float*)d_in[1];
    const float* W_all  = (const float*)d_in[2];
    const float* b_all  = (const float*)d_in[3];
    const float* U_all  = (const float*)d_in[4];
    const float* b_u    = (const float*)d_in[5];
    const float* W_d    = (const float*)d_in[6];
    const float* b_d    = (const float*)d_in[7];
    const float* W_out  = (const float*)d_in[8];
    const float* b_out  = (const float*)d_in[9];
    float* out = (float*)d_out;

    xproj_kernel<<<dim3(8, 4, 256), 256>>>(inputs, U_all, b_u);

    cudaFuncSetAttribute(scan_kernel,
                         cudaFuncAttributeMaxDynamicSharedMemorySize, SMEM_BYTES);
    scan_kernel<<<128, 512, SMEM_BYTES>>>(TI, W_all, b_all, W_d, b_d,
                                          W_out, b_out, out);
}

// round 11
// speedup vs baseline: 2.3489x; 1.1717x over previous
#include <cuda_runtime.h>
#include <cuda_fp16.h>
#include <cuda_bf16.h>

#define BB 256
#define SS 2048
#define EE 64
#define HH 128
#define G4 512   // 4*H

// x_proj scratch, GATE-INTERLEAVED: [(s*BB+b)*128 + c]*4 + g   (1.07 GB fp32)
__device__ float g_xp[(size_t)SS * BB * G4];

// ---- fast activations via MUFU.TANH ----------------------------------------
__device__ __forceinline__ float tanh_ap(float x) {
    float r;
    asm("tanh.approx.f32 %0, %1;" : "=f"(r) : "f"(x));
    return r;
}
__device__ __forceinline__ float sigm_f(float x) {
    return fmaf(0.5f, tanh_ap(0.5f * x), 0.5f);
}
__device__ __forceinline__ float tanh_f(float x) {
    return tanh_ap(x);
}

// ---- f32x2 packed-math helpers (sm_103a) ------------------------------------
typedef unsigned long long ull;

__device__ __forceinline__ ull fma2(ull a, ull b, ull c) {
    ull d;
    asm("fma.rn.f32x2 %0, %1, %2, %3;" : "=l"(d) : "l"(a), "l"(b), "l"(c));
    return d;
}
// bf16x2 (lo half = v_k, hi half = v_{k+1}) -> f32x2 (v_k, v_{k+1})
__device__ __forceinline__ ull bf2f2(unsigned int w) {
    unsigned int lo = w << 16;
    unsigned int hi = w & 0xFFFF0000u;
    ull r;
    asm("mov.b64 %0, {%1, %2};" : "=l"(r) : "r"(lo), "r"(hi));
    return r;
}
__device__ __forceinline__ float hsum2(ull v) {
    float x, y;
    asm("mov.b64 {%0, %1}, %2;" : "=f"(x), "=f"(y) : "l"(v));
    return x + y;
}
__device__ __forceinline__ unsigned int f2bf2(float hi, float lo) {
    unsigned int r;
    asm("cvt.rn.satfinite.bf16x2.f32 %0, %1, %2;" : "=r"(r) : "f"(hi), "f"(lo));
    return r;
}
__device__ __forceinline__ ull dup2(float x) {
    ull r;
    asm("mov.b64 %0, {%1, %1};" : "=l"(r) : "f"(x));
    return r;
}

// ---------------------------------------------------------------------------
// Kernel 1: x_proj = inputs @ U_all^T + b_u  (gate-interleaved output layout,
// COALESCED stores). f-tile mapping: local j in [0,64) -> f = (j&3)*128 +
// c_base + (j>>2). Each thread owns 4 consecutive j = one column c with all
// 4 gates -> one STG.128 per (b, c). Lanes span consecutive c -> coalesced.
// grid (8 c-blocks, 4 b, 256 s-blocks), 256 threads, 8 timesteps per CTA.
// ---------------------------------------------------------------------------
__global__ __launch_bounds__(256) void xproj_kernel(
    const float* __restrict__ inputs,   // [B][S][E]
    const float* __restrict__ U_all,    // [4H][E]
    const float* __restrict__ b_u)      // [4H]
{
    __shared__ float xT[64 * 68];  // [e][b]
    __shared__ float uT[64 * 68];  // [e][j]  j = cl*4 + g

    const int s0     = blockIdx.z * 8;
    const int b_base = blockIdx.y * 64;
    const int c_base = blockIdx.x * 16;    // 16 columns per CTA, all 4 gates
    const int tid    = threadIdx.x;
    const int e      = tid & 63;
    const int r0     = tid >> 6;

    // U tile: load once. j = cl*4 + g  ->  f = g*128 + c_base + cl
    #pragma unroll
    for (int i = 0; i < 16; i++) {
        int j = r0 + i * 4;
        int f = (j & 3) * 128 + c_base + (j >> 2);
        uT[e * 68 + j] = U_all[(size_t)f * EE + e];
    }

    const int bi = (tid >> 4) * 4;
    const int fi = (tid & 15) * 4;         // j base: cl = tid&15, g = 0..3
    const int cl = tid & 15;

    float4 bu;
    {
        float bv[4];
        #pragma unroll
        for (int u = 0; u < 4; u++) bv[u] = b_u[u * 128 + c_base + cl];
        bu = make_float4(bv[0], bv[1], bv[2], bv[3]);
    }

    for (int si = 0; si < 8; si++) {
        const int s = s0 + si;
        __syncthreads();
        #pragma unroll
        for (int i = 0; i < 16; i++) {
            int r = r0 + i * 4;
            xT[e * 68 + r] = inputs[((size_t)(b_base + r) * SS + s) * EE + e];
        }
        __syncthreads();

        ull acc[4][2];
        #pragma unroll
        for (int i = 0; i < 4; i++) { acc[i][0] = 0ULL; acc[i][1] = 0ULL; }

        #pragma unroll 16
        for (int k = 0; k < 64; k++) {
            float4 xv = *reinterpret_cast<const float4*>(&xT[k * 68 + bi]);
            ulonglong2 uvp = *reinterpret_cast<const ulonglong2*>(&uT[k * 68 + fi]);
            float xa[4] = {xv.x, xv.y, xv.z, xv.w};
            #pragma unroll
            for (int i = 0; i < 4; i++) {
                ull xx = dup2(xa[i]);
                acc[i][0] = fma2(xx, uvp.x, acc[i][0]);
                acc[i][1] = fma2(xx, uvp.y, acc[i][1]);
            }
        }

        #pragma unroll
        for (int i = 0; i < 4; i++) {
            const int b = b_base + bi + i;
            float av[4];
            asm("mov.b64 {%0, %1}, %2;" : "=f"(av[0]), "=f"(av[1]) : "l"(acc[i][0]));
            asm("mov.b64 {%0, %1}, %2;" : "=f"(av[2]), "=f"(av[3]) : "l"(acc[i][1]));
            float4 v;
            v.x = av[0] + bu.x;   // g=0
            v.y = av[1] + bu.y;   // g=1
            v.z = av[2] + bu.z;   // g=2
            v.w = av[3] + bu.w;   // g=3
            // one coalesced 16B store: all 4 gates of column (c_base+cl)
            *reinterpret_cast<float4*>(
                &g_xp[(((size_t)s * BB + b) * 128 + c_base + cl) * 4]) = v;
        }
    }
}

// ---------------------------------------------------------------------------
// Kernel 2: scan (R10, unchanged). 128 CTAs x 512 threads, 2 batch rows/CTA.
// ---------------------------------------------------------------------------
#define SM_WG     0                      // 64*512 words = 131072 B
#define SM_HBF    131072                 // 2*128 bf16   =    512 B (pad 1024)
#define SM_C      132096                 // 2*128 floats =   1024 B
#define SM_PREG   133120                 // 4*4*2*128 f  =  16384 B
#define SM_CPART  149504                 // 4*2*128 f    =   4096 B
#define SM_RED    153600                 // 256 floats   =   1024 B
#define SMEM_BYTES 154624

__global__ __launch_bounds__(512, 1) void scan_kernel(
    const float* __restrict__ TI,      // [B][S]
    const float* __restrict__ W_all,   // [4H][H]
    const float* __restrict__ b_all,   // [4H]
    const float* __restrict__ W_d,     // [H][H]
    const float* __restrict__ b_d,     // [H]
    const float* __restrict__ W_out,   // [1][H]
    const float* __restrict__ b_out,   // [1]
    float* __restrict__ out)           // [B]
{
    extern __shared__ char smem[];
    unsigned int* wg2 = reinterpret_cast<unsigned int*>(smem + SM_WG);
    __nv_bfloat16* hbf = reinterpret_cast<__nv_bfloat16*>(smem + SM_HBF); // [2][128]
    float* cb   = reinterpret_cast<float*>(smem + SM_C);     // [2][128] fp32
    float* preg = reinterpret_cast<float*>(smem + SM_PREG);  // [(kq*4+g)*2+m][128]
    float* cpart= reinterpret_cast<float*>(smem + SM_CPART); // [kq*2+m][128]
    float* red  = reinterpret_cast<float*>(smem + SM_RED);

    const int t  = threadIdx.x;
    const int b0 = blockIdx.x * 2;
    const int c  = t & 127;
    const int kq = t >> 7;      // 0..3 (warp-uniform)

    // ---- one-time: pack gate weights into SMEM (conflict-free layout) ----
    for (int u = t; u < 64 * 512; u += 512) {
        int r = u >> 9, rem = u & 511;
        int cc = rem >> 2, gg = rem & 3;
        float2 wv = *reinterpret_cast<const float2*>(&W_all[(size_t)(gg * 128 + cc) * HH + 2 * r]);
        wg2[u] = f2bf2(wv.y, wv.x);
    }

    // ---- wd weights -> 16 registers (step-invariant) ----
    uint4 wdr[4];
    #pragma unroll
    for (int q = 0; q < 4; q++) {
        unsigned int w[4];
        #pragma unroll
        for (int u = 0; u < 4; u++) {
            int p = q * 4 + u;
            float2 wv = *reinterpret_cast<const float2*>(&W_d[(size_t)c * HH + kq * 32 + 2 * p]);
            w[u] = f2bf2(wv.y, wv.x);
        }
        wdr[q] = make_uint4(w[0], w[1], w[2], w[3]);
    }
    const unsigned int* wdw = reinterpret_cast<const unsigned int*>(wdr);

    if (t < 256) {
        reinterpret_cast<unsigned short*>(hbf)[t] = 0;  // bf16 zero
        cb[t] = 0.0f;
    }

    // phase-B constants (threads 0..255: m = t>>7, col = c)
    float ba_r[4] = {0, 0, 0, 0}, bd_r = 0.0f, wout_r = 0.0f;
    if (t < 256) {
        #pragma unroll
        for (int g = 0; g < 4; g++) ba_r[g] = b_all[g * 128 + c];
        bd_r = b_d[c];
        wout_r = W_out[c];
    }
    const float bo = b_out[0];

    __syncthreads();

    const uint4* wgt4 = reinterpret_cast<const uint4*>(wg2) + kq * 16 * 128 + c;
    const uint4* h0q = reinterpret_cast<const uint4*>(hbf + kq * 32);
    const uint4* h1q = reinterpret_cast<const uint4*>(hbf + 128 + kq * 32);
    const ulonglong2* c0v = reinterpret_cast<const ulonglong2*>(cb + kq * 32);
    const ulonglong2* c1v = reinterpret_cast<const ulonglong2*>(cb + 128 + kq * 32);

    float out_acc = 0.0f;
    float c_reg = 0.0f;   // carried cell state for gating thread (m = t>>7, c)

    for (int s = 0; s < SS; s++) {
        // prefetch phase-B globals (hidden under phase A): ONE LDG.128 for xp
        float4 xq = make_float4(0.f, 0.f, 0.f, 0.f);
        float ti = 0.0f;
        if (t < 256) {
            const int m = t >> 7;
            xq = *reinterpret_cast<const float4*>(
                &g_xp[(((size_t)s * BB + b0 + m) * 128 + c) * 4]);
            ti = TI[(size_t)(b0 + m) * SS + s];
        }

        // ---- Phase A: quarter-k partial dots ----
        ull acc0[4] = {0ULL, 0ULL, 0ULL, 0ULL};
        ull acc1[4] = {0ULL, 0ULL, 0ULL, 0ULL};
        ull d0 = 0ULL, d1 = 0ULL;

        #pragma unroll
        for (int j = 0; j < 4; j++) {          // each j: 4 k-pairs (8 k)
            uint4 hw0 = h0q[j];                // 8 bf16 of h row 0
            uint4 hw1 = h1q[j];                // 8 bf16 of h row 1
            const unsigned int* hw0w = reinterpret_cast<const unsigned int*>(&hw0);
            const unsigned int* hw1w = reinterpret_cast<const unsigned int*>(&hw1);
            #pragma unroll
            for (int p = 0; p < 4; p++) {      // k-pair index within j
                uint4 wv = wgt4[(j * 4 + p) * 128];
                const unsigned int* w = reinterpret_cast<const unsigned int*>(&wv);
                ull hh0 = bf2f2(hw0w[p]);
                ull hh1 = bf2f2(hw1w[p]);
                #pragma unroll
                for (int g = 0; g < 4; g++) {
                    ull wg_ = bf2f2(w[g]);
                    acc0[g] = fma2(hh0, wg_, acc0[g]);
                    acc1[g] = fma2(hh1, wg_, acc1[g]);
                }
            }
            // wd: 4 k-pairs of the c-state (fp32) against register weights
            ulonglong2 ca = c0v[2 * j], cbq = c0v[2 * j + 1];
            ulonglong2 da = c1v[2 * j], dbq = c1v[2 * j + 1];
            ull wdA = bf2f2(wdw[4 * j + 0]);
            ull wdB = bf2f2(wdw[4 * j + 1]);
            ull wdC = bf2f2(wdw[4 * j + 2]);
            ull wdD = bf2f2(wdw[4 * j + 3]);
            d0 = fma2(ca.x, wdA, d0);  d0 = fma2(ca.y, wdB, d0);
            d0 = fma2(cbq.x, wdC, d0); d0 = fma2(cbq.y, wdD, d0);
            d1 = fma2(da.x, wdA, d1);  d1 = fma2(da.y, wdB, d1);
            d1 = fma2(dbq.x, wdC, d1); d1 = fma2(dbq.y, wdD, d1);
        }

        #pragma unroll
        for (int g = 0; g < 4; g++) {
            preg[((kq * 4 + g) * 2 + 0) * 128 + c] = hsum2(acc0[g]);
            preg[((kq * 4 + g) * 2 + 1) * 128 + c] = hsum2(acc1[g]);
        }
        cpart[(kq * 2 + 0) * 128 + c] = hsum2(d0);
        cpart[(kq * 2 + 1) * 128 + c] = hsum2(d1);
        __syncthreads();

        // ---- Phase B: gating (threads 0..255; (m, c)) ----
        if (t < 256) {
            const int m = t >> 7;
            const float xpv[4] = {xq.x, xq.y, xq.z, xq.w};
            float pg[4];
            #pragma unroll
            for (int g = 0; g < 4; g++) {
                pg[g] = preg[((0 * 4 + g) * 2 + m) * 128 + c]
                      + preg[((1 * 4 + g) * 2 + m) * 128 + c]
                      + preg[((2 * 4 + g) * 2 + m) * 128 + c]
                      + preg[((3 * 4 + g) * 2 + m) * 128 + c]
                      + ba_r[g] + xpv[g];
            }
            float fg = sigm_f(pg[0]);
            float ig = sigm_f(pg[1]);
            float og = sigm_f(pg[2]);
            float ct = sigm_f(pg[3]);
            float cp = cpart[(0 * 2 + m) * 128 + c] + cpart[(1 * 2 + m) * 128 + c]
                     + cpart[(2 * 2 + m) * 128 + c] + cpart[(3 * 2 + m) * 128 + c] + bd_r;

            float cs1  = tanh_f(cp);
            float cadj = (c_reg - cs1) + cs1 * ti;
            float cnew = fg * cadj + ig * ct;
            float hnew = og * tanh_f(cnew);
            c_reg = cnew;

            cb[m * 128 + c] = cnew;                       // fp32 (wd dot input)
            hbf[m * 128 + c] = __float2bfloat16_rn(hnew); // bf16 (gate dot input)
            out_acc += hnew * wout_r;
        }
        __syncthreads();
    }

    // ---- out[b] = sum_s h_s @ W_out + S * b_out ----
    if (t < 256) red[t] = out_acc;
    __syncthreads();
    if (t == 0) {
        float s0 = 0.0f;
        for (int k = 0; k < 128; k++) s0 += red[k];
        out[b0] = s0 + (float)SS * bo;
    }
    if (t == 1) {
        float s1 = 0.0f;
        for (int k = 0; k < 128; k++) s1 += red[128 + k];
        out[b0 + 1] = s1 + (float)SS * bo;
    }
}

// ---------------------------------------------------------------------------
extern "C" void kernel_launch(void* const* d_in, const int* in_sizes, int n_in,
                              void* d_out, int out_size)
{
    const float* inputs = (const float*)d_in[0];
    const float* TI     = (const float*)d_in[1];
    const float* W_all  = (const float*)d_in[2];
    const float* b_all  = (const float*)d_in[3];
    const float* U_all  = (const float*)d_in[4];
    const float* b_u    = (const float*)d_in[5];
    const float* W_d    = (const float*)d_in[6];
    const float* b_d    = (const float*)d_in[7];
    const float* W_out  = (const float*)d_in[8];
    const float* b_out  = (const float*)d_in[9];
    float* out = (float*)d_out;

    xproj_kernel<<<dim3(8, 4, 256), 256>>>(inputs, U_all, b_u);

    cudaFuncSetAttribute(scan_kernel,
                         cudaFuncAttributeMaxDynamicSharedMemorySize, SMEM_BYTES);
    scan_kernel<<<128, 512, SMEM_BYTES>>>(TI, W_all, b_all, W_d, b_d,
                                          W_out, b_out, out);
}

// round 12
// speedup vs baseline: 2.4275x; 1.0334x over previous
#include <cuda_runtime.h>
#include <cuda_fp16.h>
#include <cuda_bf16.h>

#define BB 256
#define SS 2048
#define EE 64
#define HH 128
#define G4 512   // 4*H

// x_proj scratch, GATE-INTERLEAVED: [(s*BB+b)*128 + c]*4 + g   (1.07 GB fp32)
__device__ float g_xp[(size_t)SS * BB * G4];

// ---- fast activations via MUFU.TANH ----------------------------------------
__device__ __forceinline__ float tanh_ap(float x) {
    float r;
    asm("tanh.approx.f32 %0, %1;" : "=f"(r) : "f"(x));
    return r;
}
__device__ __forceinline__ float sigm_f(float x) {
    return fmaf(0.5f, tanh_ap(0.5f * x), 0.5f);
}
__device__ __forceinline__ float tanh_f(float x) {
    return tanh_ap(x);
}

// ---- f32x2 packed-math helpers (sm_103a) ------------------------------------
typedef unsigned long long ull;

__device__ __forceinline__ ull fma2(ull a, ull b, ull c) {
    ull d;
    asm("fma.rn.f32x2 %0, %1, %2, %3;" : "=l"(d) : "l"(a), "l"(b), "l"(c));
    return d;
}
// bf16x2 -> f32x2; lo-extract via mad.lo (IMAD, fma pipe), hi via AND (alu)
__device__ __forceinline__ ull bf2f2(unsigned int w) {
    unsigned int lo, hi;
    asm("mad.lo.u32 %0, %1, 65536, 0;" : "=r"(lo) : "r"(w));
    asm("and.b32 %0, %1, 0xFFFF0000;"  : "=r"(hi) : "r"(w));
    ull r;
    asm("mov.b64 %0, {%1, %2};" : "=l"(r) : "r"(lo), "r"(hi));
    return r;
}
__device__ __forceinline__ float hsum2(ull v) {
    float x, y;
    asm("mov.b64 {%0, %1}, %2;" : "=f"(x), "=f"(y) : "l"(v));
    return x + y;
}
__device__ __forceinline__ unsigned int f2bf2(float hi, float lo) {
    unsigned int r;
    asm("cvt.rn.satfinite.bf16x2.f32 %0, %1, %2;" : "=r"(r) : "f"(hi), "f"(lo));
    return r;
}
__device__ __forceinline__ ull dup2(float x) {
    ull r;
    asm("mov.b64 %0, {%1, %1};" : "=l"(r) : "f"(x));
    return r;
}

// ---------------------------------------------------------------------------
// Kernel 1: x_proj = inputs @ U_all^T + b_u  (gate-interleaved, coalesced).
// Tile 128b x 64f (16 c x 4 g), 256 threads, each thread 8b x (1c,4g).
// Per k: 2 LDS.128 (x) + 1 LDS.128 (U) per 16 fma2. 8 timesteps per CTA.
// grid (8 c-blocks, 2 b-blocks, 256 s-blocks).
// ---------------------------------------------------------------------------
__global__ __launch_bounds__(256) void xproj_kernel(
    const float* __restrict__ inputs,   // [B][S][E]
    const float* __restrict__ U_all,    // [4H][E]
    const float* __restrict__ b_u)      // [4H]
{
    __shared__ float xT[64 * 132];  // [e][b], pitch 132
    __shared__ float uT[64 * 68];   // [e][j]  j = cl*4 + g

    const int s0     = blockIdx.z * 8;
    const int b_base = blockIdx.y * 128;
    const int c_base = blockIdx.x * 16;
    const int tid    = threadIdx.x;
    const int e      = tid & 63;
    const int r0     = tid >> 6;    // 0..3

    // U tile: load once. j = cl*4 + g  ->  f = g*128 + c_base + cl
    #pragma unroll
    for (int i = 0; i < 16; i++) {
        int j = r0 + i * 4;
        int f = (j & 3) * 128 + c_base + (j >> 2);
        uT[e * 68 + j] = U_all[(size_t)f * EE + e];
    }

    const int cl = tid & 15;        // column within c-block
    const int bq = tid >> 4;        // 0..15 : owns b rows bq*8..bq*8+7

    float4 bu;
    {
        float bv[4];
        #pragma unroll
        for (int u = 0; u < 4; u++) bv[u] = b_u[u * 128 + c_base + cl];
        bu = make_float4(bv[0], bv[1], bv[2], bv[3]);
    }

    for (int si = 0; si < 8; si++) {
        const int s = s0 + si;
        __syncthreads();   // protect xT reuse (and first-iter uT visibility)
        #pragma unroll
        for (int i = 0; i < 32; i++) {
            int b = r0 + i * 4;    // 0..127
            xT[e * 132 + b] = inputs[((size_t)(b_base + b) * SS + s) * EE + e];
        }
        __syncthreads();

        ull acc[8][2];
        #pragma unroll
        for (int i = 0; i < 8; i++) { acc[i][0] = 0ULL; acc[i][1] = 0ULL; }

        #pragma unroll 8
        for (int k = 0; k < 64; k++) {
            float4 xv0 = *reinterpret_cast<const float4*>(&xT[k * 132 + bq * 8]);
            float4 xv1 = *reinterpret_cast<const float4*>(&xT[k * 132 + bq * 8 + 4]);
            ulonglong2 uvp = *reinterpret_cast<const ulonglong2*>(&uT[k * 68 + cl * 4]);
            float xa[8] = {xv0.x, xv0.y, xv0.z, xv0.w, xv1.x, xv1.y, xv1.z, xv1.w};
            #pragma unroll
            for (int i = 0; i < 8; i++) {
                ull xx = dup2(xa[i]);
                acc[i][0] = fma2(xx, uvp.x, acc[i][0]);
                acc[i][1] = fma2(xx, uvp.y, acc[i][1]);
            }
        }

        #pragma unroll
        for (int i = 0; i < 8; i++) {
            const int b = b_base + bq * 8 + i;
            float av[4];
            asm("mov.b64 {%0, %1}, %2;" : "=f"(av[0]), "=f"(av[1]) : "l"(acc[i][0]));
            asm("mov.b64 {%0, %1}, %2;" : "=f"(av[2]), "=f"(av[3]) : "l"(acc[i][1]));
            float4 v;
            v.x = av[0] + bu.x;
            v.y = av[1] + bu.y;
            v.z = av[2] + bu.z;
            v.w = av[3] + bu.w;
            *reinterpret_cast<float4*>(
                &g_xp[(((size_t)s * BB + b) * 128 + c_base + cl) * 4]) = v;
        }
    }
}

// ---------------------------------------------------------------------------
// Kernel 2: scan. 128 CTAs x 512 threads, 2 batch rows/CTA (R10/R11 base).
// NEW: gating thread (m = t>>7 = its own kq) keeps its OWN kq partials in
// registers — skips 5 STS and reads only 12+3 partials in phase B.
// ---------------------------------------------------------------------------
#define SM_WG     0                      // 64*512 words = 131072 B
#define SM_HBF    131072                 // 2*128 bf16   =    512 B (pad 1024)
#define SM_C      132096                 // 2*128 floats =   1024 B
#define SM_PREG   133120                 // 4*4*2*128 f  =  16384 B
#define SM_CPART  149504                 // 4*2*128 f    =   4096 B
#define SM_RED    153600                 // 256 floats   =   1024 B
#define SMEM_BYTES 154624

__global__ __launch_bounds__(512, 1) void scan_kernel(
    const float* __restrict__ TI,      // [B][S]
    const float* __restrict__ W_all,   // [4H][H]
    const float* __restrict__ b_all,   // [4H]
    const float* __restrict__ W_d,     // [H][H]
    const float* __restrict__ b_d,     // [H]
    const float* __restrict__ W_out,   // [1][H]
    const float* __restrict__ b_out,   // [1]
    float* __restrict__ out)           // [B]
{
    extern __shared__ char smem[];
    unsigned int* wg2 = reinterpret_cast<unsigned int*>(smem + SM_WG);
    __nv_bfloat16* hbf = reinterpret_cast<__nv_bfloat16*>(smem + SM_HBF); // [2][128]
    float* cb   = reinterpret_cast<float*>(smem + SM_C);     // [2][128] fp32
    float* preg = reinterpret_cast<float*>(smem + SM_PREG);  // [(kq*4+g)*2+m][128]
    float* cpart= reinterpret_cast<float*>(smem + SM_CPART); // [kq*2+m][128]
    float* red  = reinterpret_cast<float*>(smem + SM_RED);

    const int t  = threadIdx.x;
    const int b0 = blockIdx.x * 2;
    const int c  = t & 127;
    const int kq = t >> 7;      // 0..3 (warp-uniform)

    // ---- one-time: pack gate weights into SMEM (conflict-free layout) ----
    for (int u = t; u < 64 * 512; u += 512) {
        int r = u >> 9, rem = u & 511;
        int cc = rem >> 2, gg = rem & 3;
        float2 wv = *reinterpret_cast<const float2*>(&W_all[(size_t)(gg * 128 + cc) * HH + 2 * r]);
        wg2[u] = f2bf2(wv.y, wv.x);
    }

    // ---- wd weights -> 16 registers (step-invariant) ----
    uint4 wdr[4];
    #pragma unroll
    for (int q = 0; q < 4; q++) {
        unsigned int w[4];
        #pragma unroll
        for (int u = 0; u < 4; u++) {
            int p = q * 4 + u;
            float2 wv = *reinterpret_cast<const float2*>(&W_d[(size_t)c * HH + kq * 32 + 2 * p]);
            w[u] = f2bf2(wv.y, wv.x);
        }
        wdr[q] = make_uint4(w[0], w[1], w[2], w[3]);
    }
    const unsigned int* wdw = reinterpret_cast<const unsigned int*>(wdr);

    if (t < 256) {
        reinterpret_cast<unsigned short*>(hbf)[t] = 0;  // bf16 zero
        cb[t] = 0.0f;
    }

    // phase-B constants (threads 0..255: m = t>>7 == kq, col = c)
    float ba_r[4] = {0, 0, 0, 0}, bd_r = 0.0f, wout_r = 0.0f;
    if (t < 256) {
        #pragma unroll
        for (int g = 0; g < 4; g++) ba_r[g] = b_all[g * 128 + c];
        bd_r = b_d[c];
        wout_r = W_out[c];
    }
    const float bo = b_out[0];

    __syncthreads();

    const uint4* wgt4 = reinterpret_cast<const uint4*>(wg2) + kq * 16 * 128 + c;
    const uint4* h0q = reinterpret_cast<const uint4*>(hbf + kq * 32);
    const uint4* h1q = reinterpret_cast<const uint4*>(hbf + 128 + kq * 32);
    const ulonglong2* c0v = reinterpret_cast<const ulonglong2*>(cb + kq * 32);
    const ulonglong2* c1v = reinterpret_cast<const ulonglong2*>(cb + 128 + kq * 32);

    float out_acc = 0.0f;
    float c_reg = 0.0f;   // carried cell state for gating thread (m = kq, c)

    for (int s = 0; s < SS; s++) {
        // prefetch phase-B globals (hidden under phase A): ONE LDG.128 for xp
        float4 xq = make_float4(0.f, 0.f, 0.f, 0.f);
        float ti = 0.0f;
        if (t < 256) {
            const int m = t >> 7;
            xq = *reinterpret_cast<const float4*>(
                &g_xp[(((size_t)s * BB + b0 + m) * 128 + c) * 4]);
            ti = TI[(size_t)(b0 + m) * SS + s];
        }

        // ---- Phase A: quarter-k partial dots ----
        ull acc0[4] = {0ULL, 0ULL, 0ULL, 0ULL};
        ull acc1[4] = {0ULL, 0ULL, 0ULL, 0ULL};
        ull d0 = 0ULL, d1 = 0ULL;

        #pragma unroll
        for (int j = 0; j < 4; j++) {          // each j: 4 k-pairs (8 k)
            uint4 hw0 = h0q[j];                // 8 bf16 of h row 0
            uint4 hw1 = h1q[j];                // 8 bf16 of h row 1
            const unsigned int* hw0w = reinterpret_cast<const unsigned int*>(&hw0);
            const unsigned int* hw1w = reinterpret_cast<const unsigned int*>(&hw1);
            #pragma unroll
            for (int p = 0; p < 4; p++) {      // k-pair index within j
                uint4 wv = wgt4[(j * 4 + p) * 128];
                const unsigned int* w = reinterpret_cast<const unsigned int*>(&wv);
                ull hh0 = bf2f2(hw0w[p]);
                ull hh1 = bf2f2(hw1w[p]);
                #pragma unroll
                for (int g = 0; g < 4; g++) {
                    ull wg_ = bf2f2(w[g]);
                    acc0[g] = fma2(hh0, wg_, acc0[g]);
                    acc1[g] = fma2(hh1, wg_, acc1[g]);
                }
            }
            // wd: 4 k-pairs of the c-state (fp32) against register weights
            ulonglong2 ca = c0v[2 * j], cbq = c0v[2 * j + 1];
            ulonglong2 da = c1v[2 * j], dbq = c1v[2 * j + 1];
            ull wdA = bf2f2(wdw[4 * j + 0]);
            ull wdB = bf2f2(wdw[4 * j + 1]);
            ull wdC = bf2f2(wdw[4 * j + 2]);
            ull wdD = bf2f2(wdw[4 * j + 3]);
            d0 = fma2(ca.x, wdA, d0);  d0 = fma2(ca.y, wdB, d0);
            d0 = fma2(cbq.x, wdC, d0); d0 = fma2(cbq.y, wdD, d0);
            d1 = fma2(da.x, wdA, d1);  d1 = fma2(da.y, wdB, d1);
            d1 = fma2(dbq.x, wdC, d1); d1 = fma2(dbq.y, wdD, d1);
        }

        // ---- partial stores (gating threads keep their OWN row in regs) ----
        float own[4], ownd = 0.0f;
        if (t < 128) {              // kq=0, gating m=0: keep row0, store row1
            #pragma unroll
            for (int g = 0; g < 4; g++) {
                own[g] = hsum2(acc0[g]);
                preg[((0 * 4 + g) * 2 + 1) * 128 + c] = hsum2(acc1[g]);
            }
            ownd = hsum2(d0);
            cpart[(0 * 2 + 1) * 128 + c] = hsum2(d1);
        } else if (t < 256) {       // kq=1, gating m=1: keep row1, store row0
            #pragma unroll
            for (int g = 0; g < 4; g++) {
                own[g] = hsum2(acc1[g]);
                preg[((1 * 4 + g) * 2 + 0) * 128 + c] = hsum2(acc0[g]);
            }
            ownd = hsum2(d1);
            cpart[(1 * 2 + 0) * 128 + c] = hsum2(d0);
        } else {                    // kq=2,3: store everything
            #pragma unroll
            for (int g = 0; g < 4; g++) {
                preg[((kq * 4 + g) * 2 + 0) * 128 + c] = hsum2(acc0[g]);
                preg[((kq * 4 + g) * 2 + 1) * 128 + c] = hsum2(acc1[g]);
            }
            cpart[(kq * 2 + 0) * 128 + c] = hsum2(d0);
            cpart[(kq * 2 + 1) * 128 + c] = hsum2(d1);
        }
        __syncthreads();

        // ---- Phase B: gating (threads 0..255; m = kq, col = c) ----
        if (t < 256) {
            const int m = t >> 7;
            const int ko = m ^ 1;   // the other low kq holding our row's partial
            const float xpv[4] = {xq.x, xq.y, xq.z, xq.w};
            float pg[4];
            #pragma unroll
            for (int g = 0; g < 4; g++) {
                pg[g] = own[g]
                      + preg[((ko * 4 + g) * 2 + m) * 128 + c]
                      + preg[((2  * 4 + g) * 2 + m) * 128 + c]
                      + preg[((3  * 4 + g) * 2 + m) * 128 + c]
                      + ba_r[g] + xpv[g];
            }
            float fg = sigm_f(pg[0]);
            float ig = sigm_f(pg[1]);
            float og = sigm_f(pg[2]);
            float ct = sigm_f(pg[3]);
            float cp = ownd + cpart[(ko * 2 + m) * 128 + c]
                     + cpart[(2 * 2 + m) * 128 + c]
                     + cpart[(3 * 2 + m) * 128 + c] + bd_r;

            float cs1  = tanh_f(cp);
            float cadj = (c_reg - cs1) + cs1 * ti;
            float cnew = fg * cadj + ig * ct;
            float hnew = og * tanh_f(cnew);
            c_reg = cnew;

            cb[m * 128 + c] = cnew;                       // fp32 (wd dot input)
            hbf[m * 128 + c] = __float2bfloat16_rn(hnew); // bf16 (gate dot input)
            out_acc += hnew * wout_r;
        }
        __syncthreads();
    }

    // ---- out[b] = sum_s h_s @ W_out + S * b_out ----
    if (t < 256) red[t] = out_acc;
    __syncthreads();
    if (t == 0) {
        float s0 = 0.0f;
        for (int k = 0; k < 128; k++) s0 += red[k];
        out[b0] = s0 + (float)SS * bo;
    }
    if (t == 1) {
        float s1 = 0.0f;
        for (int k = 0; k < 128; k++) s1 += red[128 + k];
        out[b0 + 1] = s1 + (float)SS * bo;
    }
}

// ---------------------------------------------------------------------------
extern "C" void kernel_launch(void* const* d_in, const int* in_sizes, int n_in,
                              void* d_out, int out_size)
{
    const float* inputs = (const float*)d_in[0];
    const float* TI     = (const float*)d_in[1];
    const float* W_all  = (const float*)d_in[2];
    const float* b_all  = (const float*)d_in[3];
    const float* U_all  = (const float*)d_in[4];
    const float* b_u    = (const float*)d_in[5];
    const float* W_d    = (const float*)d_in[6];
    const float* b_d    = (const float*)d_in[7];
    const float* W_out  = (const float*)d_in[8];
    const float* b_out  = (const float*)d_in[9];
    float* out = (float*)d_out;

    xproj_kernel<<<dim3(8, 2, 256), 256>>>(inputs, U_all, b_u);

    cudaFuncSetAttribute(scan_kernel,
                         cudaFuncAttributeMaxDynamicSharedMemorySize, SMEM_BYTES);
    scan_kernel<<<128, 512, SMEM_BYTES>>>(TI, W_all, b_all, W_d, b_d,
                                          W_out, b_out, out);
}

// round 13
// speedup vs baseline: 2.5134x; 1.0354x over previous
#include <cuda_runtime.h>
#include <cuda_fp16.h>
#include <cuda_bf16.h>

#define BB 256
#define SS 2048
#define EE 64
#define HH 128
#define G4 512   // 4*H

// x_proj scratch, GATE-INTERLEAVED, PRE-BIASED (b_u + b_all folded in):
// [(s*BB+b)*128 + c]*4 + g   (1.07 GB fp32)
__device__ float g_xp[(size_t)SS * BB * G4];

// ---- fast activations via MUFU.TANH ----------------------------------------
__device__ __forceinline__ float tanh_ap(float x) {
    float r;
    asm("tanh.approx.f32 %0, %1;" : "=f"(r) : "f"(x));
    return r;
}
__device__ __forceinline__ float sigm_f(float x) {
    return fmaf(0.5f, tanh_ap(0.5f * x), 0.5f);
}
__device__ __forceinline__ float tanh_f(float x) {
    return tanh_ap(x);
}

// ---- f32x2 packed-math helpers (sm_103a) ------------------------------------
typedef unsigned long long ull;

__device__ __forceinline__ ull fma2(ull a, ull b, ull c) {
    ull d;
    asm("fma.rn.f32x2 %0, %1, %2, %3;" : "=l"(d) : "l"(a), "l"(b), "l"(c));
    return d;
}
// bf16x2 (lo half = v_k, hi half = v_{k+1}) -> f32x2 (v_k, v_{k+1})
__device__ __forceinline__ ull bf2f2(unsigned int w) {
    unsigned int lo = w << 16;
    unsigned int hi = w & 0xFFFF0000u;
    ull r;
    asm("mov.b64 %0, {%1, %2};" : "=l"(r) : "r"(lo), "r"(hi));
    return r;
}
__device__ __forceinline__ float hsum2(ull v) {
    float x, y;
    asm("mov.b64 {%0, %1}, %2;" : "=f"(x), "=f"(y) : "l"(v));
    return x + y;
}
__device__ __forceinline__ unsigned int f2bf2(float hi, float lo) {
    unsigned int r;
    asm("cvt.rn.satfinite.bf16x2.f32 %0, %1, %2;" : "=r"(r) : "f"(hi), "f"(lo));
    return r;
}
__device__ __forceinline__ ull dup2(float x) {
    ull r;
    asm("mov.b64 %0, {%1, %1};" : "=l"(r) : "f"(x));
    return r;
}

// ---------------------------------------------------------------------------
// Kernel 1: x_proj = inputs @ U_all^T + (b_u + b_all)  (gate-interleaved,
// coalesced STG.128). Tile 128b x 64f (16 c x 4 g), 256 threads, 8 b-rows
// per thread, 8 timesteps per CTA. grid (8 c-blocks, 2 b-blocks, 256 s).
// ---------------------------------------------------------------------------
__global__ __launch_bounds__(256) void xproj_kernel(
    const float* __restrict__ inputs,   // [B][S][E]
    const float* __restrict__ U_all,    // [4H][E]
    const float* __restrict__ b_u,      // [4H]
    const float* __restrict__ b_all)    // [4H]
{
    __shared__ float xT[64 * 132];  // [e][b], pitch 132
    __shared__ float uT[64 * 68];   // [e][j]  j = cl*4 + g

    const int s0     = blockIdx.z * 8;
    const int b_base = blockIdx.y * 128;
    const int c_base = blockIdx.x * 16;
    const int tid    = threadIdx.x;
    const int e      = tid & 63;
    const int r0     = tid >> 6;    // 0..3

    // U tile: load once. j = cl*4 + g  ->  f = g*128 + c_base + cl
    #pragma unroll
    for (int i = 0; i < 16; i++) {
        int j = r0 + i * 4;
        int f = (j & 3) * 128 + c_base + (j >> 2);
        uT[e * 68 + j] = U_all[(size_t)f * EE + e];
    }

    const int cl = tid & 15;        // column within c-block
    const int bq = tid >> 4;        // 0..15 : owns b rows bq*8..bq*8+7

    float4 bu;
    {
        float bv[4];
        #pragma unroll
        for (int u = 0; u < 4; u++) {
            int f = u * 128 + c_base + cl;
            bv[u] = b_u[f] + b_all[f];     // fold b_all in
        }
        bu = make_float4(bv[0], bv[1], bv[2], bv[3]);
    }

    for (int si = 0; si < 8; si++) {
        const int s = s0 + si;
        __syncthreads();   // protect xT reuse (and first-iter uT visibility)
        #pragma unroll
        for (int i = 0; i < 32; i++) {
            int b = r0 + i * 4;    // 0..127
            xT[e * 132 + b] = inputs[((size_t)(b_base + b) * SS + s) * EE + e];
        }
        __syncthreads();

        ull acc[8][2];
        #pragma unroll
        for (int i = 0; i < 8; i++) { acc[i][0] = 0ULL; acc[i][1] = 0ULL; }

        #pragma unroll 8
        for (int k = 0; k < 64; k++) {
            float4 xv0 = *reinterpret_cast<const float4*>(&xT[k * 132 + bq * 8]);
            float4 xv1 = *reinterpret_cast<const float4*>(&xT[k * 132 + bq * 8 + 4]);
            ulonglong2 uvp = *reinterpret_cast<const ulonglong2*>(&uT[k * 68 + cl * 4]);
            float xa[8] = {xv0.x, xv0.y, xv0.z, xv0.w, xv1.x, xv1.y, xv1.z, xv1.w};
            #pragma unroll
            for (int i = 0; i < 8; i++) {
                ull xx = dup2(xa[i]);
                acc[i][0] = fma2(xx, uvp.x, acc[i][0]);
                acc[i][1] = fma2(xx, uvp.y, acc[i][1]);
            }
        }

        #pragma unroll
        for (int i = 0; i < 8; i++) {
            const int b = b_base + bq * 8 + i;
            float av[4];
            asm("mov.b64 {%0, %1}, %2;" : "=f"(av[0]), "=f"(av[1]) : "l"(acc[i][0]));
            asm("mov.b64 {%0, %1}, %2;" : "=f"(av[2]), "=f"(av[3]) : "l"(acc[i][1]));
            float4 v;
            v.x = av[0] + bu.x;
            v.y = av[1] + bu.y;
            v.z = av[2] + bu.z;
            v.w = av[3] + bu.w;
            *reinterpret_cast<float4*>(
                &g_xp[(((size_t)s * BB + b) * 128 + c_base + cl) * 4]) = v;
        }
    }
}

// ---------------------------------------------------------------------------
// Kernel 2: scan. 128 CTAs x 512 threads, 2 batch rows/CTA.
// h state is FP32 in SMEM (broadcast reads are ~free; kills 32 bf2f2/thread).
// Gate weights bf16x2 SMEM (conflict-free), wd weights in 16 regs.
// Own-kq partials kept in registers by gating threads. 2 barriers/step.
// ---------------------------------------------------------------------------
#define SM_WG     0                      // 64*512 words = 131072 B
#define SM_HF     131072                 // 2*128 floats =   1024 B
#define SM_C      132096                 // 2*128 floats =   1024 B
#define SM_PREG   133120                 // 4*4*2*128 f  =  16384 B
#define SM_CPART  149504                 // 4*2*128 f    =   4096 B
#define SM_RED    153600                 // 256 floats   =   1024 B
#define SMEM_BYTES 154624

__global__ __launch_bounds__(512, 1) void scan_kernel(
    const float* __restrict__ TI,      // [B][S]
    const float* __restrict__ W_all,   // [4H][H]
    const float* __restrict__ W_d,     // [H][H]
    const float* __restrict__ b_d,     // [H]
    const float* __restrict__ W_out,   // [1][H]
    const float* __restrict__ b_out,   // [1]
    float* __restrict__ out)           // [B]
{
    extern __shared__ char smem[];
    unsigned int* wg2 = reinterpret_cast<unsigned int*>(smem + SM_WG);
    float* hf   = reinterpret_cast<float*>(smem + SM_HF);    // [2][128] fp32
    float* cb   = reinterpret_cast<float*>(smem + SM_C);     // [2][128] fp32
    float* preg = reinterpret_cast<float*>(smem + SM_PREG);  // [(kq*4+g)*2+m][128]
    float* cpart= reinterpret_cast<float*>(smem + SM_CPART); // [kq*2+m][128]
    float* red  = reinterpret_cast<float*>(smem + SM_RED);

    const int t  = threadIdx.x;
    const int b0 = blockIdx.x * 2;
    const int c  = t & 127;
    const int kq = t >> 7;      // 0..3 (warp-uniform)

    // ---- one-time: pack gate weights into SMEM (conflict-free layout) ----
    for (int u = t; u < 64 * 512; u += 512) {
        int r = u >> 9, rem = u & 511;
        int cc = rem >> 2, gg = rem & 3;
        float2 wv = *reinterpret_cast<const float2*>(&W_all[(size_t)(gg * 128 + cc) * HH + 2 * r]);
        wg2[u] = f2bf2(wv.y, wv.x);
    }

    // ---- wd weights -> 16 registers (step-invariant) ----
    uint4 wdr[4];
    #pragma unroll
    for (int q = 0; q < 4; q++) {
        unsigned int w[4];
        #pragma unroll
        for (int u = 0; u < 4; u++) {
            int p = q * 4 + u;
            float2 wv = *reinterpret_cast<const float2*>(&W_d[(size_t)c * HH + kq * 32 + 2 * p]);
            w[u] = f2bf2(wv.y, wv.x);
        }
        wdr[q] = make_uint4(w[0], w[1], w[2], w[3]);
    }
    const unsigned int* wdw = reinterpret_cast<const unsigned int*>(wdr);

    if (t < 256) { hf[t] = 0.0f; cb[t] = 0.0f; }

    // phase-B constants (threads 0..255: m = t>>7 == kq, col = c)
    float bd_r = 0.0f, wout_r = 0.0f;
    if (t < 256) {
        bd_r = b_d[c];
        wout_r = W_out[c];
    }
    const float bo = b_out[0];

    __syncthreads();

    const uint4* wgt4 = reinterpret_cast<const uint4*>(wg2) + kq * 16 * 128 + c;
    const ulonglong2* h0v = reinterpret_cast<const ulonglong2*>(hf + kq * 32);
    const ulonglong2* h1v = reinterpret_cast<const ulonglong2*>(hf + 128 + kq * 32);
    const ulonglong2* c0v = reinterpret_cast<const ulonglong2*>(cb + kq * 32);
    const ulonglong2* c1v = reinterpret_cast<const ulonglong2*>(cb + 128 + kq * 32);

    float out_acc = 0.0f;
    float c_reg = 0.0f;   // carried cell state for gating thread (m = kq, c)

    for (int s = 0; s < SS; s++) {
        // prefetch phase-B globals (hidden under phase A): ONE LDG.128 for xp
        float4 xq = make_float4(0.f, 0.f, 0.f, 0.f);
        float ti = 0.0f;
        if (t < 256) {
            const int m = t >> 7;
            xq = *reinterpret_cast<const float4*>(
                &g_xp[(((size_t)s * BB + b0 + m) * 128 + c) * 4]);
            ti = TI[(size_t)(b0 + m) * SS + s];
        }

        // ---- Phase A: quarter-k partial dots (h fp32, no h decompress) ----
        ull acc0[4] = {0ULL, 0ULL, 0ULL, 0ULL};
        ull acc1[4] = {0ULL, 0ULL, 0ULL, 0ULL};
        ull d0 = 0ULL, d1 = 0ULL;

        #pragma unroll
        for (int j = 0; j < 4; j++) {          // each j: 4 k-pairs (8 k)
            ulonglong2 ha0 = h0v[2 * j];       // h row0, k-pairs 4j, 4j+1
            ulonglong2 hb0 = h0v[2 * j + 1];   // h row0, k-pairs 4j+2, 4j+3
            ulonglong2 ha1 = h1v[2 * j];
            ulonglong2 hb1 = h1v[2 * j + 1];
            ull hp0[4] = {ha0.x, ha0.y, hb0.x, hb0.y};
            ull hp1[4] = {ha1.x, ha1.y, hb1.x, hb1.y};
            #pragma unroll
            for (int p = 0; p < 4; p++) {      // k-pair index within j
                uint4 wv = wgt4[(j * 4 + p) * 128];
                const unsigned int* w = reinterpret_cast<const unsigned int*>(&wv);
                #pragma unroll
                for (int g = 0; g < 4; g++) {
                    ull wg_ = bf2f2(w[g]);
                    acc0[g] = fma2(hp0[p], wg_, acc0[g]);
                    acc1[g] = fma2(hp1[p], wg_, acc1[g]);
                }
            }
            // wd: 4 k-pairs of the c-state (fp32) against register weights
            ulonglong2 ca = c0v[2 * j], cbq = c0v[2 * j + 1];
            ulonglong2 da = c1v[2 * j], dbq = c1v[2 * j + 1];
            ull wdA = bf2f2(wdw[4 * j + 0]);
            ull wdB = bf2f2(wdw[4 * j + 1]);
            ull wdC = bf2f2(wdw[4 * j + 2]);
            ull wdD = bf2f2(wdw[4 * j + 3]);
            d0 = fma2(ca.x, wdA, d0);  d0 = fma2(ca.y, wdB, d0);
            d0 = fma2(cbq.x, wdC, d0); d0 = fma2(cbq.y, wdD, d0);
            d1 = fma2(da.x, wdA, d1);  d1 = fma2(da.y, wdB, d1);
            d1 = fma2(dbq.x, wdC, d1); d1 = fma2(dbq.y, wdD, d1);
        }

        // ---- partial stores (gating threads keep their OWN row in regs) ----
        float own[4], ownd = 0.0f;
        if (t < 128) {              // kq=0, gating m=0: keep row0, store row1
            #pragma unroll
            for (int g = 0; g < 4; g++) {
                own[g] = hsum2(acc0[g]);
                preg[((0 * 4 + g) * 2 + 1) * 128 + c] = hsum2(acc1[g]);
            }
            ownd = hsum2(d0);
            cpart[(0 * 2 + 1) * 128 + c] = hsum2(d1);
        } else if (t < 256) {       // kq=1, gating m=1: keep row1, store row0
            #pragma unroll
            for (int g = 0; g < 4; g++) {
                own[g] = hsum2(acc1[g]);
                preg[((1 * 4 + g) * 2 + 0) * 128 + c] = hsum2(acc0[g]);
            }
            ownd = hsum2(d1);
            cpart[(1 * 2 + 0) * 128 + c] = hsum2(d0);
        } else {                    // kq=2,3: store everything
            #pragma unroll
            for (int g = 0; g < 4; g++) {
                preg[((kq * 4 + g) * 2 + 0) * 128 + c] = hsum2(acc0[g]);
                preg[((kq * 4 + g) * 2 + 1) * 128 + c] = hsum2(acc1[g]);
            }
            cpart[(kq * 2 + 0) * 128 + c] = hsum2(d0);
            cpart[(kq * 2 + 1) * 128 + c] = hsum2(d1);
        }
        __syncthreads();

        // ---- Phase B: gating (threads 0..255; m = kq, col = c) ----
        if (t < 256) {
            const int m = t >> 7;
            const int ko = m ^ 1;   // the other low kq holding our row's partial
            const float xpv[4] = {xq.x, xq.y, xq.z, xq.w};
            float pg[4];
            #pragma unroll
            for (int g = 0; g < 4; g++) {
                pg[g] = own[g]
                      + preg[((ko * 4 + g) * 2 + m) * 128 + c]
                      + preg[((2  * 4 + g) * 2 + m) * 128 + c]
                      + preg[((3  * 4 + g) * 2 + m) * 128 + c]
                      + xpv[g];                    // bias pre-folded into xp
            }
            float fg = sigm_f(pg[0]);
            float ig = sigm_f(pg[1]);
            float og = sigm_f(pg[2]);
            float ct = sigm_f(pg[3]);
            float cp = ownd + cpart[(ko * 2 + m) * 128 + c]
                     + cpart[(2 * 2 + m) * 128 + c]
                     + cpart[(3 * 2 + m) * 128 + c] + bd_r;

            float cs1  = tanh_f(cp);
            float cadj = (c_reg - cs1) + cs1 * ti;
            float cnew = fg * cadj + ig * ct;
            float hnew = og * tanh_f(cnew);
            c_reg = cnew;

            cb[m * 128 + c] = cnew;   // fp32
            hf[m * 128 + c] = hnew;   // fp32 (broadcast reads are cheap)
            out_acc += hnew * wout_r;
        }
        __syncthreads();
    }

    // ---- out[b] = sum_s h_s @ W_out + S * b_out ----
    if (t < 256) red[t] = out_acc;
    __syncthreads();
    if (t == 0) {
        float s0 = 0.0f;
        for (int k = 0; k < 128; k++) s0 += red[k];
        out[b0] = s0 + (float)SS * bo;
    }
    if (t == 1) {
        float s1 = 0.0f;
        for (int k = 0; k < 128; k++) s1 += red[128 + k];
        out[b0 + 1] = s1 + (float)SS * bo;
    }
}

// ---------------------------------------------------------------------------
extern "C" void kernel_launch(void* const* d_in, const int* in_sizes, int n_in,
                              void* d_out, int out_size)
{
    const float* inputs = (const float*)d_in[0];
    const float* TI     = (const float*)d_in[1];
    const float* W_all  = (const float*)d_in[2];
    const float* b_all  = (const float*)d_in[3];
    const float* U_all  = (const float*)d_in[4];
    const float* b_u    = (const float*)d_in[5];
    const float* W_d    = (const float*)d_in[6];
    const float* b_d    = (const float*)d_in[7];
    const float* W_out  = (const float*)d_in[8];
    const float* b_out  = (const float*)d_in[9];
    float* out = (float*)d_out;

    xproj_kernel<<<dim3(8, 2, 256), 256>>>(inputs, U_all, b_u, b_all);

    cudaFuncSetAttribute(scan_kernel,
                         cudaFuncAttributeMaxDynamicSharedMemorySize, SMEM_BYTES);
    scan_kernel<<<128, 512, SMEM_BYTES>>>(TI, W_all, W_d, b_d,
                                          W_out, b_out, out);
}